// round 5
// baseline (speedup 1.0000x reference)
#include <cuda_runtime.h>
#include <cuda_bf16.h>
#include <math.h>

// Problem constants
#define B_   16
#define C_   64
#define H_   160
#define W_   160
#define PD   32
#define HW   (H_*W_)
#define LK_  13
#define PADK 6
#define TX   16
#define TYR  16
#define ITH  (TYR + 2*PADK)   // 28
#define ITW  (TX  + 2*PADK)   // 28
#define CHUNK 4               // ci per input chunk
#define IN_CH    (ITH*ITW)        // 784
#define IN_CHUNK (CHUNK*IN_CH)    // 3136
#define FSTRIDE 32                // [tap][co] stride
#define FSLICE  (169*FSTRIDE)     // 5408 floats per ci slice
#define NFB 3                     // filter slice buffers (distance-2 staging needs 3)

typedef unsigned long long ull;

__device__ float g_gap[B_ * PD];
__device__ float g_dk[B_ * PD * 9];

// ---------------- packed f32x2 helpers ----------------
__device__ __forceinline__ ull dup2(float a) {
    ull r;
    asm("mov.b64 %0, {%1, %1};" : "=l"(r) : "f"(a));
    return r;
}
__device__ __forceinline__ void fma2(ull& d, ull a, ull b) {
    asm("fma.rn.f32x2 %0, %1, %2, %0;" : "+l"(d) : "l"(a), "l"(b));
}
__device__ __forceinline__ float2 unpk(ull v) {
    float2 f;
    asm("mov.b64 {%0, %1}, %2;" : "=f"(f.x), "=f"(f.y) : "l"(v));
    return f;
}
__device__ __forceinline__ void cp4(float* dst, const float* src) {
    unsigned d = (unsigned)__cvta_generic_to_shared(dst);
    asm volatile("cp.async.ca.shared.global [%0], [%1], 4;" :: "r"(d), "l"(src));
}
// predicated cp.async: zero-fill shared when out of bounds
__device__ __forceinline__ void cp4z(float* dst, const float* src, bool ok, const float* safe) {
    unsigned d = (unsigned)__cvta_generic_to_shared(dst);
    int sz = ok ? 4 : 0;
    const float* s = ok ? src : safe;
    asm volatile("cp.async.ca.shared.global [%0], [%1], 4, %2;" :: "r"(d), "l"(s), "r"(sz));
}

// ---------------- kernel 1: GAP over H,W for first 32 ch ----------------
__global__ void gap_kernel(const float* __restrict__ x) {
    int bc = blockIdx.x;
    int b  = bc >> 5;
    int c  = bc & 31;
    const float4* p = (const float4*)(x + (size_t)(b * C_ + c) * HW);
    float s = 0.f;
    for (int i = threadIdx.x; i < HW / 4; i += 256) {
        float4 v = p[i];
        s += (v.x + v.y) + (v.z + v.w);
    }
    __shared__ float red[256];
    red[threadIdx.x] = s;
    __syncthreads();
    for (int st = 128; st > 0; st >>= 1) {
        if (threadIdx.x < st) red[threadIdx.x] += red[threadIdx.x + st];
        __syncthreads();
    }
    if (threadIdx.x == 0) g_gap[bc] = red[0] * (1.0f / (float)HW);
}

// ---------------- kernel 2: tiny MLP -> dk[b][c][3][3] ----------------
__global__ void mlp_kernel(const float* __restrict__ w1, const float* __restrict__ b1,
                           const float* __restrict__ w2, const float* __restrict__ b2) {
    __shared__ float h[B_ * 16];
    int t = threadIdx.x;           // 288 threads
    if (t < 256) {
        int b = t >> 4, j = t & 15;
        float s = b1[j];
#pragma unroll
        for (int c = 0; c < 32; c++) s += g_gap[b * 32 + c] * w1[j * 32 + c];
        h[t] = 0.5f * s * (1.0f + erff(s * 0.7071067811865476f));
    }
    __syncthreads();
    for (int idx = t; idx < B_ * 288; idx += 288) {
        int b = idx / 288, k = idx % 288;
        float s = b2[k];
#pragma unroll
        for (int j = 0; j < 16; j++) s += h[b * 16 + j] * w2[k * 16 + j];
        g_dk[idx] = s;
    }
}

// ---------------- main kernel ----------------
// 13x13 conv (32->32), dynamic 3x3 folded into filter slice diagonal.
// block 256: tx=tid&15, tz=(tid>>4)&1 (co half), ty=tid>>5; 2 px x 16 co per thread.
// grid (10,10,16). 2 CTAs/SM (91.1 KB smem).
__global__ __launch_bounds__(256, 2)
void conv_main(const float* __restrict__ x, const float* __restrict__ flt,
               float* __restrict__ out) {
    extern __shared__ float sm[];
    float* sIn  = sm;                         // 2 * 3136
    float* sFlt = sm + 2 * IN_CHUNK;          // 3 * 5408
    float* sDk  = sFlt + NFB * FSLICE;        // 288

    const int b   = blockIdx.z;
    const int x0  = blockIdx.x * TX;
    const int y0  = blockIdx.y * TYR;
    const int tid = threadIdx.x;
    const int tx  = tid & 15;
    const int tz  = (tid >> 4) & 1;
    const int ty  = tid >> 5;
    const int coB = tz * 16;

    const float* xb = x + (size_t)b * C_ * HW;

    for (int i = tid; i < PD * 9; i += 256) sDk[i] = g_dk[b * PD * 9 + i];

    // input chunk k (4 ci) -> buffer (k&1)
    #define STAGE_CHUNK(k) do {                                               \
        float* dstb = sIn + ((k) & 1) * IN_CHUNK;                             \
        for (int i = tid; i < IN_CHUNK; i += 256) {                           \
            int cl  = i / IN_CH;                                              \
            int rem = i - cl * IN_CH;                                         \
            int r = rem / ITW, c = rem - r * ITW;                             \
            int gy = y0 - PADK + r, gx = x0 - PADK + c;                       \
            bool ok = ((unsigned)gy < (unsigned)H_) & ((unsigned)gx < (unsigned)W_); \
            const float* src = xb + ((k) * CHUNK + cl) * HW + gy * W_ + gx;   \
            cp4z(dstb + i, src, ok, xb);                                      \
        }                                                                     \
    } while (0)

    // filter slice ci -> buffer bi (0..2), layout [tap][co]
    #define STAGE_FILTER(ci, bi) do {                                         \
        float* fdst = sFlt + (bi) * FSLICE;                                   \
        int co = tid >> 3, t0 = tid & 7;                                      \
        const float* src = flt + ((size_t)co * PD + (ci)) * 169;              \
        for (int t = t0; t < 169; t += 8) cp4(fdst + t * FSTRIDE + co, src + t); \
    } while (0)

    // prologue: G0 = {chunk0, filter0->buf0}, G1 = {filter1->buf1}
    STAGE_CHUNK(0);
    STAGE_FILTER(0, 0);
    asm volatile("cp.async.commit_group;" ::: "memory");
    STAGE_FILTER(1, 1);
    asm volatile("cp.async.commit_group;" ::: "memory");

    ull acc[2][8];
#pragma unroll
    for (int p = 0; p < 2; p++)
#pragma unroll
        for (int q = 0; q < 8; q++) acc[p][q] = 0ULL;

    int fbi = 0;                 // ci % 3
    int sbi = 2;                 // (ci+2) % 3  (staging target)
    for (int ci = 0; ci < PD; ci++) {
        asm volatile("cp.async.wait_group 1;" ::: "memory");
        __syncthreads();                         // slice ci + its chunk visible

        float* fb = sFlt + fbi * FSLICE;
        // fold dynamic 3x3 into the diagonal (co==ci) of this freshly staged slice
        if (tid < 9) {
            int i = tid / 3, j = tid - 3 * i;
            fb[((i + 5) * LK_ + (j + 5)) * FSTRIDE + ci] += sDk[ci * 9 + tid];
        }
        // stage slice ci+2 into buffer (ci+2)%3; input chunk 2 iters ahead of use
        int nc = ci + 2;
        if (nc < PD) {
            if ((nc & (CHUNK - 1)) == 0) STAGE_CHUNK(nc >> 2);
            STAGE_FILTER(nc, sbi);
        }
        asm volatile("cp.async.commit_group;" ::: "memory");  // empty group ok
        __syncthreads();                         // dk fold visible

        const float* inC = sIn + ((ci >> 2) & 1) * IN_CHUNK + (ci & (CHUNK - 1)) * IN_CH;
#pragma unroll 1
        for (int ky = 0; ky < LK_; ky++) {
            const float* rA   = inC + (ty + ky) * ITW + tx;
            const float* rB   = rA + 8 * ITW;
            const float* wrow = fb + (ky * LK_) * FSTRIDE + coB;
#pragma unroll
            for (int kx = 0; kx < LK_; kx++) {
                const float* wp = wrow + kx * FSTRIDE;
                ulonglong2 pA = *(const ulonglong2*)(wp);        // co 0..3
                ulonglong2 pB = *(const ulonglong2*)(wp + 4);    // co 4..7
                ulonglong2 pC = *(const ulonglong2*)(wp + 8);    // co 8..11
                ulonglong2 pD = *(const ulonglong2*)(wp + 12);   // co 12..15
                ull dA = dup2(rA[kx]);
                ull dB = dup2(rB[kx]);
                fma2(acc[0][0], dA, pA.x); fma2(acc[0][1], dA, pA.y);
                fma2(acc[0][2], dA, pB.x); fma2(acc[0][3], dA, pB.y);
                fma2(acc[0][4], dA, pC.x); fma2(acc[0][5], dA, pC.y);
                fma2(acc[0][6], dA, pD.x); fma2(acc[0][7], dA, pD.y);
                fma2(acc[1][0], dB, pA.x); fma2(acc[1][1], dB, pA.y);
                fma2(acc[1][2], dB, pB.x); fma2(acc[1][3], dB, pB.y);
                fma2(acc[1][4], dB, pC.x); fma2(acc[1][5], dB, pC.y);
                fma2(acc[1][6], dB, pD.x); fma2(acc[1][7], dB, pD.y);
            }
        }
        fbi = (fbi == 2) ? 0 : fbi + 1;
        sbi = (sbi == 2) ? 0 : sbi + 1;
    }

    // ---- epilogue: store (dyn conv already folded into filter) ----
#pragma unroll
    for (int p = 0; p < 2; p++) {
        int gy = y0 + ty + p * 8;
#pragma unroll
        for (int q = 0; q < 8; q++) {
            float2 v = unpk(acc[p][q]);
            int c = coB + 2 * q;
            size_t off = (((size_t)b * C_ + c) * H_ + gy) * W_ + x0 + tx;
            out[off]      = v.x;
            out[off + HW] = v.y;
        }
    }

    // ---- fused x2 passthrough copy (channels 32..63, this tile) ----
    for (int idx = tid; idx < PD * TYR * (TX / 4); idx += 256) {   // 2048 float4
        int ch2 = idx >> 6;
        int rem = idx & 63;
        int row = rem >> 2, c4 = rem & 3;
        size_t off = (((size_t)b * C_ + PD + ch2) * H_ + y0 + row) * W_ + x0 + c4 * 4;
        *(float4*)(out + off) = *(const float4*)(x + off);
    }
    #undef STAGE_CHUNK
    #undef STAGE_FILTER
}

// ---------------- launch ----------------
extern "C" void kernel_launch(void* const* d_in, const int* in_sizes, int n_in,
                              void* d_out, int out_size) {
    const float* x  = (const float*)d_in[0];
    const float* lk = (const float*)d_in[1];
    const float* w1 = (const float*)d_in[2];
    const float* b1 = (const float*)d_in[3];
    const float* w2 = (const float*)d_in[4];
    const float* b2 = (const float*)d_in[5];
    float* out = (float*)d_out;

    const int smem_bytes = (2 * IN_CHUNK + NFB * FSLICE + PD * 9) * (int)sizeof(float); // 91136
    cudaFuncSetAttribute(conv_main, cudaFuncAttributeMaxDynamicSharedMemorySize, smem_bytes);

    gap_kernel<<<B_ * PD, 256>>>(x);
    mlp_kernel<<<1, 288>>>(w1, b1, w2, b2);

    dim3 grid(W_ / TX, H_ / TYR, B_);
    conv_main<<<grid, 256, smem_bytes>>>(x, lk, out);
}